// round 1
// baseline (speedup 1.0000x reference)
#include <cuda_runtime.h>

#define DIM 31
#define PAD 32
#define NMAX 500000
#define EMAX 2000000
#define GMAX 4096
#define BN_EPS 1e-5f

// ---------------- scratch (static device allocations) ----------------
__device__ float g_x[(size_t)NMAX * PAD];     // 64 MB padded node features
__device__ float g_agg[(size_t)NMAX * PAD];   // 64 MB aggregate / intermediate y
__device__ float g_pooled[GMAX * PAD];        // pooled per-graph features
__device__ float g_ha[GMAX * 256];
__device__ float g_hb[GMAX * 256];
__device__ float g_c1[GMAX * 1024];
__device__ float g_c2[GMAX * 256];
__device__ float g_sums[2 * PAD];             // column sums + sumsq for BN

// ---------------- init: pack x into padded layout, zero agg ----------------
__global__ void k_init(const float* __restrict__ x, int N) {
    int total = N * PAD;
    for (int t = blockIdx.x * blockDim.x + threadIdx.x; t < total;
         t += gridDim.x * blockDim.x) {
        int c = t & (PAD - 1);
        int i = t >> 5;
        g_x[t] = (c < DIM) ? x[i * DIM + c] : 0.f;
        g_agg[t] = 0.f;
    }
    if (blockIdx.x == 0 && threadIdx.x < 2 * PAD) g_sums[threadIdx.x] = 0.f;
}

// ---------------- scatter: agg[dst] += x[src] ----------------
__global__ void k_scatter(const int* __restrict__ src, const int* __restrict__ dst, int E) {
    if (blockIdx.x == 0 && threadIdx.x < 2 * PAD) g_sums[threadIdx.x] = 0.f;
    int total = E * 8;
    for (int t = blockIdx.x * blockDim.x + threadIdx.x; t < total;
         t += gridDim.x * blockDim.x) {
        int e = t >> 3;
        int g = t & 7;
        int s = __ldg(src + e);
        int d = __ldg(dst + e);
        float4 v = *(const float4*)(g_x + (size_t)s * PAD + g * 4);
        float* p = g_agg + (size_t)d * PAD + g * 4;
        atomicAdd(p + 0, v.x);
        atomicAdd(p + 1, v.y);
        atomicAdd(p + 2, v.z);
        if (g < 7) atomicAdd(p + 3, v.w);  // col 31 is padding (always 0)
    }
}

// ---------------- per-node MLP: y = relu(relu((x+agg)@W1+b1)@W2+b2) -> agg ----------------
__global__ void __launch_bounds__(128) k_mlp(const float* __restrict__ W1,
                                             const float* __restrict__ b1,
                                             const float* __restrict__ W2,
                                             const float* __restrict__ b2, int N) {
    __shared__ float sW1[DIM * PAD];
    __shared__ float sW2[DIM * PAD];
    __shared__ float sb1[DIM], sb2[DIM];
    for (int idx = threadIdx.x; idx < DIM * DIM; idx += blockDim.x) {
        int i = idx / DIM, o = idx % DIM;
        sW1[i * PAD + o] = W1[idx];
        sW2[i * PAD + o] = W2[idx];
    }
    if (threadIdx.x < DIM) {
        sb1[threadIdx.x] = b1[threadIdx.x];
        sb2[threadIdx.x] = b2[threadIdx.x];
    }
    __syncthreads();

    int n = blockIdx.x * blockDim.x + threadIdx.x;
    if (n >= N) return;

    float v[PAD];
    {
        const float4* xr = (const float4*)(g_x + (size_t)n * PAD);
        const float4* ar = (const float4*)(g_agg + (size_t)n * PAD);
#pragma unroll
        for (int g = 0; g < 8; g++) {
            float4 a = xr[g];
            float4 b = ar[g];
            v[4 * g + 0] = a.x + b.x;
            v[4 * g + 1] = a.y + b.y;
            v[4 * g + 2] = a.z + b.z;
            v[4 * g + 3] = a.w + b.w;
        }
    }

    float acc[DIM];
#pragma unroll
    for (int o = 0; o < DIM; o++) acc[o] = sb1[o];
#pragma unroll
    for (int i = 0; i < DIM; i++) {
        float xi = v[i];
        const float4* wr = (const float4*)(sW1 + i * PAD);
#pragma unroll
        for (int gq = 0; gq < 8; gq++) {
            float4 w = wr[gq];
            int o = gq * 4;
            acc[o + 0] += xi * w.x;
            acc[o + 1] += xi * w.y;
            acc[o + 2] += xi * w.z;
            if (o + 3 < DIM) acc[o + 3] += xi * w.w;
        }
    }
    float tt[DIM];
#pragma unroll
    for (int o = 0; o < DIM; o++) tt[o] = fmaxf(acc[o], 0.f);

#pragma unroll
    for (int o = 0; o < DIM; o++) acc[o] = sb2[o];
#pragma unroll
    for (int i = 0; i < DIM; i++) {
        float xi = tt[i];
        const float4* wr = (const float4*)(sW2 + i * PAD);
#pragma unroll
        for (int gq = 0; gq < 8; gq++) {
            float4 w = wr[gq];
            int o = gq * 4;
            acc[o + 0] += xi * w.x;
            acc[o + 1] += xi * w.y;
            acc[o + 2] += xi * w.z;
            if (o + 3 < DIM) acc[o + 3] += xi * w.w;
        }
    }

    float y[PAD];
#pragma unroll
    for (int o = 0; o < DIM; o++) y[o] = fmaxf(acc[o], 0.f);
    y[31] = 0.f;

    float4* outp = (float4*)(g_agg + (size_t)n * PAD);
#pragma unroll
    for (int g = 0; g < 8; g++)
        outp[g] = make_float4(y[4 * g], y[4 * g + 1], y[4 * g + 2], y[4 * g + 3]);
}

// ---------------- column sums of y (stored in g_agg) for BN ----------------
__global__ void k_colsum(int N) {
    int c = threadIdx.x & 31;
    int warp = threadIdx.x >> 5;
    int wpb = blockDim.x >> 5;
    float s = 0.f, q = 0.f;
    for (int r = blockIdx.x * wpb + warp; r < N; r += gridDim.x * wpb) {
        float v = g_agg[(size_t)r * PAD + c];
        s += v;
        q += v * v;
    }
    __shared__ float sh[2 * PAD];
    if (threadIdx.x < 2 * PAD) sh[threadIdx.x] = 0.f;
    __syncthreads();
    atomicAdd(&sh[c], s);
    atomicAdd(&sh[PAD + c], q);
    __syncthreads();
    if (threadIdx.x < 2 * PAD) atomicAdd(&g_sums[threadIdx.x], sh[threadIdx.x]);
}

// ---------------- BN normalize: x = (y-m)*istd*g+b ; zero agg ----------------
__global__ void k_bn(const float* __restrict__ gamma, const float* __restrict__ beta,
                     int N, float invN) {
    __shared__ float sc[PAD], sf[PAD];
    if (threadIdx.x < PAD) {
        float scale = 0.f, shift = 0.f;
        int c = threadIdx.x;
        if (c < DIM) {
            float m = g_sums[c] * invN;
            float var = g_sums[PAD + c] * invN - m * m;
            float istd = rsqrtf(var + BN_EPS);
            scale = gamma[c] * istd;
            shift = beta[c] - m * scale;
        }
        sc[threadIdx.x] = scale;
        sf[threadIdx.x] = shift;
    }
    __syncthreads();
    int total = N * 8;
    float4* ya = (float4*)g_agg;
    float4* xa = (float4*)g_x;
    for (int t = blockIdx.x * blockDim.x + threadIdx.x; t < total;
         t += gridDim.x * blockDim.x) {
        float4 y = ya[t];
        int cb = (t & 7) * 4;
        float4 o;
        o.x = y.x * sc[cb + 0] + sf[cb + 0];
        o.y = y.y * sc[cb + 1] + sf[cb + 1];
        o.z = y.z * sc[cb + 2] + sf[cb + 2];
        o.w = y.w * sc[cb + 3] + sf[cb + 3];
        xa[t] = o;
        ya[t] = make_float4(0.f, 0.f, 0.f, 0.f);
    }
}

// ---------------- pooling: pooled[batch[n]] += x[n] ----------------
__global__ void k_pool(const int* __restrict__ batch, int N) {
    int total = N * 8;
    for (int t = blockIdx.x * blockDim.x + threadIdx.x; t < total;
         t += gridDim.x * blockDim.x) {
        int n = t >> 3;
        int g = t & 7;
        int b = __ldg(batch + n);
        float4 v = ((const float4*)g_x)[t];
        float* p = g_pooled + (size_t)b * PAD + g * 4;
        atomicAdd(p + 0, v.x);
        atomicAdd(p + 1, v.y);
        atomicAdd(p + 2, v.z);
        if (g < 7) atomicAdd(p + 3, v.w);
    }
}

// ---------------- per-graph fc: h = relu(pooled @ W[31,256] + b) ----------------
__global__ void k_fcbr(const float* __restrict__ W, const float* __restrict__ b,
                       float* __restrict__ out, int G) {
    __shared__ float p[PAD];
    int g = blockIdx.x;
    if (threadIdx.x < PAD) p[threadIdx.x] = g_pooled[g * PAD + threadIdx.x];
    __syncthreads();
    int o = threadIdx.x;  // 256 threads
    float acc = __ldg(b + o);
#pragma unroll
    for (int i = 0; i < DIM; i++) acc += p[i] * __ldg(W + i * 256 + o);
    out[g * 256 + o] = fmaxf(acc, 0.f);
}

// ---------------- tiled SGEMM: C = act((A [+A2]) @ B + bias) ----------------
template <bool SUM2, bool RELU>
__global__ void k_gemm(const float* __restrict__ A, const float* __restrict__ A2,
                       const float* __restrict__ B, const float* __restrict__ bias,
                       float* __restrict__ C, int M, int N, int K) {
    const int BM = 64, BN = 64, BK = 16;
    __shared__ float As[BK][BM];
    __shared__ float Bs[BK][BN];
    int tx = threadIdx.x % 16, ty = threadIdx.x / 16;
    int row0 = blockIdx.y * BM, col0 = blockIdx.x * BN;
    float acc[4][4] = {};
    for (int k0 = 0; k0 < K; k0 += BK) {
        for (int i = threadIdx.x; i < BM * BK; i += 256) {
            int r = i / BK, c = i % BK;
            float v = A[(size_t)(row0 + r) * K + k0 + c];
            if (SUM2) v += A2[(size_t)(row0 + r) * K + k0 + c];
            As[c][r] = v;
        }
        for (int i = threadIdx.x; i < BK * BN; i += 256) {
            int r = i / BN, c = i % BN;
            Bs[r][c] = B[(size_t)(k0 + r) * N + col0 + c];
        }
        __syncthreads();
#pragma unroll
        for (int k = 0; k < BK; k++) {
            float a[4], bb[4];
#pragma unroll
            for (int u = 0; u < 4; u++) a[u] = As[k][ty * 4 + u];
#pragma unroll
            for (int u = 0; u < 4; u++) bb[u] = Bs[k][tx * 4 + u];
#pragma unroll
            for (int u = 0; u < 4; u++)
#pragma unroll
                for (int w = 0; w < 4; w++) acc[u][w] += a[u] * bb[w];
        }
        __syncthreads();
    }
#pragma unroll
    for (int u = 0; u < 4; u++)
#pragma unroll
        for (int w = 0; w < 4; w++) {
            int r = row0 + ty * 4 + u;
            int cc = col0 + tx * 4 + w;
            float val = acc[u][w] + bias[cc];
            if (RELU) val = fmaxf(val, 0.f);
            C[(size_t)r * N + cc] = val;
        }
}

// ---------------- final projection: out[g] = c2[g] @ out_W + out_b ----------------
__global__ void k_out(const float* __restrict__ W, const float* __restrict__ b,
                      float* __restrict__ out, int G) {
    __shared__ float sW[512];
    for (int i = threadIdx.x; i < 512; i += blockDim.x) sW[i] = W[i];
    __syncthreads();
    int g = blockIdx.x * blockDim.x + threadIdx.x;
    if (g >= G) return;
    const float4* row = (const float4*)(g_c2 + (size_t)g * 256);
    float a0 = b[0], a1 = b[1];
#pragma unroll 8
    for (int i = 0; i < 64; i++) {
        float4 v = row[i];
        int o = i * 4;
        a0 += v.x * sW[2 * o + 0] + v.y * sW[2 * o + 2] + v.z * sW[2 * o + 4] + v.w * sW[2 * o + 6];
        a1 += v.x * sW[2 * o + 1] + v.y * sW[2 * o + 3] + v.z * sW[2 * o + 5] + v.w * sW[2 * o + 7];
    }
    out[g * 2 + 0] = a0;
    out[g * 2 + 1] = a1;
}

// ---------------- launch ----------------
extern "C" void kernel_launch(void* const* d_in, const int* in_sizes, int n_in,
                              void* d_out, int out_size) {
    const float* x_a = (const float*)d_in[0];
    const int* ei_a = (const int*)d_in[1];
    const int* batch_a = (const int*)d_in[2];
    const float* x_b = (const float*)d_in[3];
    const int* ei_b = (const int*)d_in[4];
    const int* batch_b = (const int*)d_in[5];
    const float* W1s = (const float*)d_in[6];
    const float* b1s = (const float*)d_in[7];
    const float* W2s = (const float*)d_in[8];
    const float* b2s = (const float*)d_in[9];
    const float* gammas = (const float*)d_in[10];
    const float* betas = (const float*)d_in[11];
    const float* fcxW = (const float*)d_in[12];
    const float* fcxb = (const float*)d_in[13];
    const float* fc1W = (const float*)d_in[14];
    const float* fc1b = (const float*)d_in[15];
    const float* fc2W = (const float*)d_in[16];
    const float* fc2b = (const float*)d_in[17];
    const float* outW = (const float*)d_in[18];
    const float* outb = (const float*)d_in[19];

    int N = in_sizes[0] / DIM;
    int E = in_sizes[1] / 2;
    int G = out_size / 2;
    float invN = 1.f / (float)N;

    float* pooled_ptr;
    float* ha_ptr;
    float* hb_ptr;
    float* c1_ptr;
    float* c2_ptr;
    cudaGetSymbolAddress((void**)&pooled_ptr, g_pooled);
    cudaGetSymbolAddress((void**)&ha_ptr, g_ha);
    cudaGetSymbolAddress((void**)&hb_ptr, g_hb);
    cudaGetSymbolAddress((void**)&c1_ptr, g_c1);
    cudaGetSymbolAddress((void**)&c2_ptr, g_c2);

    for (int br = 0; br < 2; br++) {
        const float* x = br ? x_b : x_a;
        const int* ei = br ? ei_b : ei_a;
        const int* batch = br ? batch_b : batch_a;
        float* h = br ? hb_ptr : ha_ptr;

        k_init<<<2048, 256>>>(x, N);
        for (int l = 0; l < 5; l++) {
            k_scatter<<<4096, 256>>>(ei, ei + E, E);
            int mb = (N + 127) / 128;
            k_mlp<<<mb, 128>>>(W1s + l * DIM * DIM, b1s + l * DIM,
                               W2s + l * DIM * DIM, b2s + l * DIM, N);
            k_colsum<<<1184, 256>>>(N);
            k_bn<<<2048, 256>>>(gammas + l * DIM, betas + l * DIM, N, invN);
        }
        cudaMemsetAsync(pooled_ptr, 0, (size_t)GMAX * PAD * sizeof(float));
        k_pool<<<2048, 256>>>(batch, N);
        k_fcbr<<<G, 256>>>(fcxW, fcxb, h, G);
    }

    dim3 g1(1024 / 64, G / 64);
    k_gemm<true, true><<<g1, 256>>>(ha_ptr, hb_ptr, fc1W, fc1b, c1_ptr, G, 1024, 256);
    dim3 g2(256 / 64, G / 64);
    k_gemm<false, true><<<g2, 256>>>(c1_ptr, nullptr, fc2W, fc2b, c2_ptr, G, 256, 1024);
    k_out<<<(G + 255) / 256, 256>>>(outW, outb, (float*)d_out, G);
}